// round 1
// baseline (speedup 1.0000x reference)
#include <cuda_runtime.h>
#include <math.h>
#include <stdint.h>

#define Bb 4
#define S 2048
#define D 512
#define H 4
#define HD 128
#define M_TOT (Bb*S)      // 8192
#define D2 (2*D)          // 1024
#define LN_EPS 1e-5f

// ---------------- scratch (static device globals; no allocation) ----------------
__device__ float g_h[(size_t)M_TOT * D2];       // 33.5 MB
__device__ float g_se_pre[(size_t)M_TOT * D];   // 16.8 MB
__device__ float g_se[(size_t)M_TOT * D];
__device__ float g_q[(size_t)M_TOT * D];
__device__ float g_k[(size_t)M_TOT * D];
__device__ float g_v[(size_t)M_TOT * D];
__device__ float g_ctx[(size_t)M_TOT * D];
__device__ float g_scores[(size_t)Bb * H * S * S];  // 268 MB

// ---------------- generic NN GEMM: C = act(A@B + bias [+ resid]) ----------------
// A [M,K] row-major (ld=K), B [K,N] row-major (ld=N), C [M,N] (ld=N).
// Tiles: 128x128x8, 256 threads, 8x8 per thread.
template<bool RELU, bool RESID>
__global__ void gemm128(const float* __restrict__ A, const float* __restrict__ Bm,
                        const float* __restrict__ bias, const float* __restrict__ resid,
                        float* __restrict__ C, int M, int N, int K)
{
    __shared__ float As[8][128];
    __shared__ float Bs[8][128];

    const int t  = threadIdx.x;
    const int bm = blockIdx.y * 128;
    const int bn = blockIdx.x * 128;
    const int tr = t >> 4;          // 0..15
    const int tc = t & 15;          // 0..15

    float acc[8][8];
#pragma unroll
    for (int i = 0; i < 8; i++)
#pragma unroll
        for (int j = 0; j < 8; j++) acc[i][j] = 0.f;

    const int am = t >> 1;              // 0..127
    const int ac = (t & 1) * 4;         // 0 or 4
    const int bk = t >> 5;              // 0..7
    const int bn4 = (t & 31) * 4;       // 0..124

    for (int k0 = 0; k0 < K; k0 += 8) {
        // load A tile (transpose into As[k][m])
        float4 a4 = *(const float4*)(A + (size_t)(bm + am) * K + k0 + ac);
        As[ac + 0][am] = a4.x; As[ac + 1][am] = a4.y;
        As[ac + 2][am] = a4.z; As[ac + 3][am] = a4.w;
        // load B tile
        float4 b4 = *(const float4*)(Bm + (size_t)(k0 + bk) * N + bn + bn4);
        *(float4*)&Bs[bk][bn4] = b4;
        __syncthreads();

#pragma unroll
        for (int kk = 0; kk < 8; kk++) {
            float a[8], b[8];
            *(float4*)(a)     = *(const float4*)&As[kk][tr * 8];
            *(float4*)(a + 4) = *(const float4*)&As[kk][tr * 8 + 4];
            *(float4*)(b)     = *(const float4*)&Bs[kk][tc * 8];
            *(float4*)(b + 4) = *(const float4*)&Bs[kk][tc * 8 + 4];
#pragma unroll
            for (int i = 0; i < 8; i++)
#pragma unroll
                for (int j = 0; j < 8; j++)
                    acc[i][j] = fmaf(a[i], b[j], acc[i][j]);
        }
        __syncthreads();
    }

    // epilogue
#pragma unroll
    for (int i = 0; i < 8; i++) {
        const int row = bm + tr * 8 + i;
#pragma unroll
        for (int j = 0; j < 8; j += 4) {
            const int col = bn + tc * 8 + j;
            float4 o;
            o.x = acc[i][j + 0] + __ldg(bias + col + 0);
            o.y = acc[i][j + 1] + __ldg(bias + col + 1);
            o.z = acc[i][j + 2] + __ldg(bias + col + 2);
            o.w = acc[i][j + 3] + __ldg(bias + col + 3);
            if (RESID) {
                float4 r = *(const float4*)(resid + (size_t)row * N + col);
                o.x += r.x; o.y += r.y; o.z += r.z; o.w += r.w;
            }
            if (RELU) {
                o.x = fmaxf(o.x, 0.f); o.y = fmaxf(o.y, 0.f);
                o.z = fmaxf(o.z, 0.f); o.w = fmaxf(o.w, 0.f);
            }
            *(float4*)(C + (size_t)row * N + col) = o;
        }
    }
}

// ---------------- scores = Q@K^T / sqrt(HD) - alpha*dist2  (NT GEMM, batched over b,h) --
// grid: (S/128, S/128, B*H). q/k are [B*S, D], head h at columns h*HD.
__global__ void score_kernel(const float* __restrict__ pos, const float* __restrict__ alpha_p)
{
    __shared__ float As[8][128];
    __shared__ float Bs[8][128];

    const int z = blockIdx.z;
    const int b = z / H, h = z % H;
    const float* Aq = g_q + (size_t)b * S * D + h * HD;
    const float* Bk = g_k + (size_t)b * S * D + h * HD;
    float* Cs = g_scores + (size_t)z * S * S;

    const int t  = threadIdx.x;
    const int bm = blockIdx.y * 128;
    const int bn = blockIdx.x * 128;
    const int tr = t >> 4, tc = t & 15;

    float acc[8][8];
#pragma unroll
    for (int i = 0; i < 8; i++)
#pragma unroll
        for (int j = 0; j < 8; j++) acc[i][j] = 0.f;

    const int am = t >> 1;
    const int ac = (t & 1) * 4;

    for (int k0 = 0; k0 < HD; k0 += 8) {
        float4 a4 = *(const float4*)(Aq + (size_t)(bm + am) * D + k0 + ac);
        As[ac + 0][am] = a4.x; As[ac + 1][am] = a4.y;
        As[ac + 2][am] = a4.z; As[ac + 3][am] = a4.w;
        float4 b4 = *(const float4*)(Bk + (size_t)(bn + am) * D + k0 + ac);
        Bs[ac + 0][am] = b4.x; Bs[ac + 1][am] = b4.y;
        Bs[ac + 2][am] = b4.z; Bs[ac + 3][am] = b4.w;
        __syncthreads();

#pragma unroll
        for (int kk = 0; kk < 8; kk++) {
            float a[8], bb[8];
            *(float4*)(a)      = *(const float4*)&As[kk][tr * 8];
            *(float4*)(a + 4)  = *(const float4*)&As[kk][tr * 8 + 4];
            *(float4*)(bb)     = *(const float4*)&Bs[kk][tc * 8];
            *(float4*)(bb + 4) = *(const float4*)&Bs[kk][tc * 8 + 4];
#pragma unroll
            for (int i = 0; i < 8; i++)
#pragma unroll
                for (int j = 0; j < 8; j++)
                    acc[i][j] = fmaf(a[i], bb[j], acc[i][j]);
        }
        __syncthreads();
    }

    const float scale = 0.08838834764831845f;   // 1/sqrt(128)
    const float alpha = __ldg(alpha_p);
    const float* pb = pos + (size_t)b * S * 3;

    float pi[8][3], sqi[8], pj[8][3], sqj[8];
#pragma unroll
    for (int i = 0; i < 8; i++) {
        const int r = bm + tr * 8 + i;
        pi[i][0] = pb[(size_t)r * 3 + 0];
        pi[i][1] = pb[(size_t)r * 3 + 1];
        pi[i][2] = pb[(size_t)r * 3 + 2];
        sqi[i] = pi[i][0]*pi[i][0] + pi[i][1]*pi[i][1] + pi[i][2]*pi[i][2];
    }
#pragma unroll
    for (int j = 0; j < 8; j++) {
        const int c = bn + tc * 8 + j;
        pj[j][0] = pb[(size_t)c * 3 + 0];
        pj[j][1] = pb[(size_t)c * 3 + 1];
        pj[j][2] = pb[(size_t)c * 3 + 2];
        sqj[j] = pj[j][0]*pj[j][0] + pj[j][1]*pj[j][1] + pj[j][2]*pj[j][2];
    }

#pragma unroll
    for (int i = 0; i < 8; i++) {
        const int row = bm + tr * 8 + i;
#pragma unroll
        for (int j = 0; j < 8; j++) {
            const int col = bn + tc * 8 + j;
            float dot = pi[i][0]*pj[j][0] + pi[i][1]*pj[j][1] + pi[i][2]*pj[j][2];
            float d2 = fmaxf(sqi[i] + sqj[j] - 2.f * dot, 0.f);
            Cs[(size_t)row * S + col] = acc[i][j] * scale - alpha * d2;
        }
    }
}

// ---------------- row softmax over g_scores (row length S) ----------------
__global__ void softmax_kernel()
{
    __shared__ float red[256];
    const size_t row = blockIdx.x;
    float* p = g_scores + row * (size_t)S;
    const int t = threadIdx.x;

    float v[8];
    float mx = -INFINITY;
#pragma unroll
    for (int i = 0; i < 8; i++) { v[i] = p[t + i * 256]; mx = fmaxf(mx, v[i]); }

    red[t] = mx; __syncthreads();
    for (int s2 = 128; s2 > 0; s2 >>= 1) {
        if (t < s2) red[t] = fmaxf(red[t], red[t + s2]);
        __syncthreads();
    }
    mx = red[0]; __syncthreads();

    float sum = 0.f;
#pragma unroll
    for (int i = 0; i < 8; i++) { v[i] = expf(v[i] - mx); sum += v[i]; }
    red[t] = sum; __syncthreads();
    for (int s2 = 128; s2 > 0; s2 >>= 1) {
        if (t < s2) red[t] += red[t + s2];
        __syncthreads();
    }
    const float inv = 1.f / red[0];
#pragma unroll
    for (int i = 0; i < 8; i++) p[t + i * 256] = v[i] * inv;
}

// ---------------- ctx = P @ V  (NN, K=S, N=HD=128, batched over b,h) ----------------
// grid: (1, S/128, B*H)
__global__ void pv_kernel()
{
    __shared__ float As[8][128];
    __shared__ float Bs[8][128];

    const int z = blockIdx.z;
    const int b = z / H, h = z % H;
    const float* Ap = g_scores + (size_t)z * S * S;
    const float* Bv = g_v   + (size_t)b * S * D + h * HD;
    float* Cc       = g_ctx + (size_t)b * S * D + h * HD;

    const int t  = threadIdx.x;
    const int bm = blockIdx.y * 128;
    const int tr = t >> 4, tc = t & 15;

    float acc[8][8];
#pragma unroll
    for (int i = 0; i < 8; i++)
#pragma unroll
        for (int j = 0; j < 8; j++) acc[i][j] = 0.f;

    const int am = t >> 1;
    const int ac = (t & 1) * 4;
    const int bk = t >> 5;
    const int bn4 = (t & 31) * 4;

    for (int k0 = 0; k0 < S; k0 += 8) {
        float4 a4 = *(const float4*)(Ap + (size_t)(bm + am) * S + k0 + ac);
        As[ac + 0][am] = a4.x; As[ac + 1][am] = a4.y;
        As[ac + 2][am] = a4.z; As[ac + 3][am] = a4.w;
        float4 b4 = *(const float4*)(Bv + (size_t)(k0 + bk) * D + bn4);
        *(float4*)&Bs[bk][bn4] = b4;
        __syncthreads();

#pragma unroll
        for (int kk = 0; kk < 8; kk++) {
            float a[8], bb[8];
            *(float4*)(a)      = *(const float4*)&As[kk][tr * 8];
            *(float4*)(a + 4)  = *(const float4*)&As[kk][tr * 8 + 4];
            *(float4*)(bb)     = *(const float4*)&Bs[kk][tc * 8];
            *(float4*)(bb + 4) = *(const float4*)&Bs[kk][tc * 8 + 4];
#pragma unroll
            for (int i = 0; i < 8; i++)
#pragma unroll
                for (int j = 0; j < 8; j++)
                    acc[i][j] = fmaf(a[i], bb[j], acc[i][j]);
        }
        __syncthreads();
    }

#pragma unroll
    for (int i = 0; i < 8; i++) {
        const int row = bm + tr * 8 + i;
#pragma unroll
        for (int j = 0; j < 8; j += 4)
            *(float4*)(Cc + (size_t)row * D + tc * 8 + j) = *(float4*)&acc[i][j];
    }
}

// ---------------- LayerNorm: out = LN(x [+ x2]) over last dim D ----------------
// grid: M_TOT blocks, 128 threads, 4 elems/thread
__global__ void ln_kernel(const float* __restrict__ x, const float* __restrict__ x2,
                          const float* __restrict__ gamma, const float* __restrict__ beta,
                          float* __restrict__ out)
{
    __shared__ float red[128];
    const int row = blockIdx.x, t = threadIdx.x;
    const size_t base = (size_t)row * D + t * 4;

    float4 v = *(const float4*)(x + base);
    if (x2) {
        float4 w = *(const float4*)(x2 + base);
        v.x += w.x; v.y += w.y; v.z += w.z; v.w += w.w;
    }

    red[t] = v.x + v.y + v.z + v.w; __syncthreads();
    for (int s2 = 64; s2 > 0; s2 >>= 1) {
        if (t < s2) red[t] += red[t + s2];
        __syncthreads();
    }
    const float mean = red[0] * (1.f / D); __syncthreads();

    float dx = v.x - mean, dy = v.y - mean, dz = v.z - mean, dw = v.w - mean;
    red[t] = dx*dx + dy*dy + dz*dz + dw*dw; __syncthreads();
    for (int s2 = 64; s2 > 0; s2 >>= 1) {
        if (t < s2) red[t] += red[t + s2];
        __syncthreads();
    }
    const float inv = rsqrtf(red[0] * (1.f / D) + LN_EPS);

    float4 g = *(const float4*)(gamma + t * 4);
    float4 bt = *(const float4*)(beta + t * 4);
    float4 o;
    o.x = dx * inv * g.x + bt.x;
    o.y = dy * inv * g.y + bt.y;
    o.z = dz * inv * g.z + bt.z;
    o.w = dw * inv * g.w + bt.w;
    *(float4*)(out + base) = o;
}

// ---------------- host launch ----------------
extern "C" void kernel_launch(void* const* d_in, const int* in_sizes, int n_in,
                              void* d_out, int out_size)
{
    const float* input   = (const float*)d_in[0];
    const float* pos     = (const float*)d_in[1];
    const float* We      = (const float*)d_in[2];
    const float* be      = (const float*)d_in[3];
    const float* Ws      = (const float*)d_in[4];
    const float* bs      = (const float*)d_in[5];
    const float* gamma   = (const float*)d_in[6];
    const float* beta    = (const float*)d_in[7];
    const float* Wq      = (const float*)d_in[8];
    const float* bq      = (const float*)d_in[9];
    const float* Wk      = (const float*)d_in[10];
    const float* bk      = (const float*)d_in[11];
    const float* Wv      = (const float*)d_in[12];
    const float* bv      = (const float*)d_in[13];
    const float* alpha_p = (const float*)d_in[14];
    float* out = (float*)d_out;

    float *h, *se_pre, *se, *q, *k, *v, *ctx;
    cudaGetSymbolAddress((void**)&h,      g_h);
    cudaGetSymbolAddress((void**)&se_pre, g_se_pre);
    cudaGetSymbolAddress((void**)&se,     g_se);
    cudaGetSymbolAddress((void**)&q,      g_q);
    cudaGetSymbolAddress((void**)&k,      g_k);
    cudaGetSymbolAddress((void**)&v,      g_v);
    cudaGetSymbolAddress((void**)&ctx,    g_ctx);

    // 1. h = relu(input @ We + be)          [8192,1024]
    gemm128<true,  false><<<dim3(D2 / 128, M_TOT / 128), 256>>>(input, We, be, nullptr, h, M_TOT, D2, D);
    // 2. se_pre = input + h @ Ws + bs       [8192,512]
    gemm128<false, true ><<<dim3(D  / 128, M_TOT / 128), 256>>>(h, Ws, bs, input, se_pre, M_TOT, D, D2);
    // 3. se = LN(se_pre)
    ln_kernel<<<M_TOT, 128>>>(se_pre, nullptr, gamma, beta, se);
    // 4. q/k/v projections
    gemm128<false, false><<<dim3(D / 128, M_TOT / 128), 256>>>(se, Wq, bq, nullptr, q, M_TOT, D, D);
    gemm128<false, false><<<dim3(D / 128, M_TOT / 128), 256>>>(se, Wk, bk, nullptr, k, M_TOT, D, D);
    gemm128<false, false><<<dim3(D / 128, M_TOT / 128), 256>>>(se, Wv, bv, nullptr, v, M_TOT, D, D);
    // 5. scores = q@k^T/sqrt(HD) - alpha*dist2
    score_kernel<<<dim3(S / 128, S / 128, Bb * H), 256>>>(pos, alpha_p);
    // 6. softmax rows
    softmax_kernel<<<Bb * H * S, 256>>>();
    // 7. ctx = P @ v
    pv_kernel<<<dim3(1, S / 128, Bb * H), 256>>>();
    // 8. out = LN(se + ctx)
    ln_kernel<<<M_TOT, 128>>>(se, ctx, gamma, beta, out);
}

// round 3
// speedup vs baseline: 2.7781x; 2.7781x over previous
#include <cuda_runtime.h>
#include <math.h>
#include <stdint.h>

#define Bb 4
#define S 2048
#define D 512
#define H 4
#define HD 128
#define M_TOT (Bb*S)      // 8192
#define D2 (2*D)          // 1024
#define LN_EPS 1e-5f

// ------------------------------------------------------------------ scratch
__device__ float g_h[(size_t)M_TOT * D2];
__device__ float g_se_pre[(size_t)M_TOT * D];
__device__ float g_se[(size_t)M_TOT * D];
__device__ float g_qk[2 * (size_t)M_TOT * D];     // q then k
__device__ float g_vt[(size_t)M_TOT * D];         // [B][D][S] (V^T per batch)
__device__ float g_ctx[(size_t)M_TOT * D];
__device__ float g_scores[(size_t)Bb * H * S * S];
__device__ float g_wet[1024 * 512];               // We^T [1024,512]
__device__ float g_wst[512 * 1024];               // Ws^T [512,1024]
__device__ float g_wqkv[3 * 512 * 512];           // Wq^T,Wk^T,Wv^T

// ------------------------------------------------------------------ utils
__device__ __forceinline__ uint32_t f2tf(float f) {
    uint32_t u; asm("cvt.rna.tf32.f32 %0, %1;" : "=r"(u) : "f"(f)); return u;
}

__device__ __forceinline__ void mma_tf32(float c[4], const uint32_t a[4], const uint32_t b[2]) {
    asm volatile(
        "mma.sync.aligned.m16n8k8.row.col.f32.tf32.tf32.f32 "
        "{%0,%1,%2,%3}, {%4,%5,%6,%7}, {%8,%9}, {%0,%1,%2,%3};"
        : "+f"(c[0]), "+f"(c[1]), "+f"(c[2]), "+f"(c[3])
        : "r"(a[0]), "r"(a[1]), "r"(a[2]), "r"(a[3]), "r"(b[0]), "r"(b[1]));
}

#define LDA 36   // padded smem leading dim (floats)

// ------------------------------------------------------------------ mainloop
// Computes 128x128 C-tile (fp32) over K, A [128,K] row-major (lda), Bt [128,K]
// row-major (ldb) — i.e. C = A @ Bt^T. K % 32 == 0. acc indexed [mt][nt][4].
__device__ __forceinline__ void mma_mainloop(
    const float* __restrict__ Ap, long long lda,
    const float* __restrict__ Bp, long long ldb,
    int K, uint32_t (*As)[LDA], uint32_t (*Bs)[LDA], float acc[4][4][4])
{
    const int tid  = threadIdx.x;
    const int w    = tid >> 5, lane = tid & 31;
    const int gid  = lane >> 2, tig = lane & 3;
    const int wm   = w & 1, wn = w >> 1;

    const int srow = tid >> 3;        // 0..31 (stage row base, +32 per rep)
    const int sc4  = (tid & 7) * 4;   // 0..28 step 4

    float4 pa[4], pb[4];
#pragma unroll
    for (int i = 0; i < 4; i++) {
        pa[i] = *(const float4*)(Ap + (long long)(srow + i * 32) * lda + sc4);
        pb[i] = *(const float4*)(Bp + (long long)(srow + i * 32) * ldb + sc4);
    }

    const int nchunk = K >> 5;
    for (int c = 0; c < nchunk; c++) {
        __syncthreads();
#pragma unroll
        for (int i = 0; i < 4; i++) {
            const int r = srow + i * 32;
            As[r][sc4 + 0] = f2tf(pa[i].x); As[r][sc4 + 1] = f2tf(pa[i].y);
            As[r][sc4 + 2] = f2tf(pa[i].z); As[r][sc4 + 3] = f2tf(pa[i].w);
            Bs[r][sc4 + 0] = f2tf(pb[i].x); Bs[r][sc4 + 1] = f2tf(pb[i].y);
            Bs[r][sc4 + 2] = f2tf(pb[i].z); Bs[r][sc4 + 3] = f2tf(pb[i].w);
        }
        __syncthreads();

        if (c + 1 < nchunk) {
            const int k0 = (c + 1) << 5;
#pragma unroll
            for (int i = 0; i < 4; i++) {
                pa[i] = *(const float4*)(Ap + (long long)(srow + i * 32) * lda + k0 + sc4);
                pb[i] = *(const float4*)(Bp + (long long)(srow + i * 32) * ldb + k0 + sc4);
            }
        }

#pragma unroll
        for (int k8 = 0; k8 < 4; k8++) {
            const int kb = k8 * 8;
            uint32_t af[4][4], bf[4][2];
#pragma unroll
            for (int mt = 0; mt < 4; mt++) {
                const int r = wm * 64 + mt * 16 + gid;
                af[mt][0] = As[r][kb + tig];
                af[mt][1] = As[r + 8][kb + tig];
                af[mt][2] = As[r][kb + tig + 4];
                af[mt][3] = As[r + 8][kb + tig + 4];
            }
#pragma unroll
            for (int nt = 0; nt < 4; nt++) {
                const int n = wn * 32 + nt * 8 + gid;
                bf[nt][0] = Bs[n][kb + tig];
                bf[nt][1] = Bs[n][kb + tig + 4];
            }
#pragma unroll
            for (int mt = 0; mt < 4; mt++)
#pragma unroll
                for (int nt = 0; nt < 4; nt++)
                    mma_tf32(acc[mt][nt], af[mt], bf[nt]);
        }
    }
}

// ------------------------------------------------------------------ generic linear GEMM
// C[z] = act(A[z] @ Bt[z]^T + bias_z [+ resid]); Bt [N,K] row-major.
__global__ void __launch_bounds__(256)
mma_gemm(const float* __restrict__ A, long long lda, long long Azb, long long Azh,
         const float* __restrict__ Bt, long long ldb, long long Bzb, long long Bzh,
         float* __restrict__ C, long long ldc, long long Czb, long long Czh,
         const float* b0, const float* b1, const float* b2,
         const float* __restrict__ resid, float* __restrict__ vt, int vt_z,
         int relu, int K, int zdiv)
{
    __shared__ uint32_t As[128][LDA];
    __shared__ uint32_t Bs[128][LDA];

    const int tid = threadIdx.x;
    const int z = blockIdx.z;
    const long long zb = z / zdiv, zh = z % zdiv;

    const float* Ap = A + zb * Azb + zh * Azh + (long long)blockIdx.y * 128 * lda;
    const float* Bp = Bt + zb * Bzb + zh * Bzh + (long long)blockIdx.x * 128 * ldb;

    float acc[4][4][4];
#pragma unroll
    for (int i = 0; i < 4; i++)
#pragma unroll
        for (int j = 0; j < 4; j++)
#pragma unroll
            for (int e = 0; e < 4; e++) acc[i][j][e] = 0.f;

    mma_mainloop(Ap, lda, Bp, ldb, K, As, Bs, acc);

    const float* bias = (z == 0) ? b0 : (z == 1) ? b1 : b2;
    const int w = tid >> 5, lane = tid & 31;
    const int gid = lane >> 2, tig = lane & 3;
    const int wm = w & 1, wn = w >> 1;
    float* Cz = C + zb * Czb + zh * Czh;
    const bool dotrans = (vt != nullptr) && (z == vt_z);

#pragma unroll
    for (int mt = 0; mt < 4; mt++) {
        const long long r0 = (long long)blockIdx.y * 128 + wm * 64 + mt * 16 + gid;
        const long long r1 = r0 + 8;
#pragma unroll
        for (int nt = 0; nt < 4; nt++) {
            const long long cb = (long long)blockIdx.x * 128 + wn * 32 + nt * 8 + tig * 2;
            float v0 = acc[mt][nt][0], v1 = acc[mt][nt][1];
            float v2 = acc[mt][nt][2], v3 = acc[mt][nt][3];
            if (bias) {
                const float bx = __ldg(bias + cb), by = __ldg(bias + cb + 1);
                v0 += bx; v1 += by; v2 += bx; v3 += by;
            }
            if (resid) {
                const float2 q0 = *(const float2*)(resid + r0 * ldc + cb);
                const float2 q1 = *(const float2*)(resid + r1 * ldc + cb);
                v0 += q0.x; v1 += q0.y; v2 += q1.x; v3 += q1.y;
            }
            if (relu) {
                v0 = fmaxf(v0, 0.f); v1 = fmaxf(v1, 0.f);
                v2 = fmaxf(v2, 0.f); v3 = fmaxf(v3, 0.f);
            }
            if (dotrans) {
                // V^T layout: vt[b][d][s]
                const long long b0r = r0 >> 11, s0 = r0 & (S - 1);
                const long long b1r = r1 >> 11, s1 = r1 & (S - 1);
                float* vb0 = vt + b0r * ((long long)D * S);
                float* vb1 = vt + b1r * ((long long)D * S);
                vb0[cb * S + s0] = v0; vb0[(cb + 1) * S + s0] = v1;
                vb1[cb * S + s1] = v2; vb1[(cb + 1) * S + s1] = v3;
            } else {
                *(float2*)(Cz + r0 * ldc + cb) = make_float2(v0, v1);
                *(float2*)(Cz + r1 * ldc + cb) = make_float2(v2, v3);
            }
        }
    }
}

// ------------------------------------------------------------------ scores
// scores[z] = q@k^T / sqrt(HD) - alpha * dist2, z = b*H + h.
__global__ void __launch_bounds__(256)
mma_score(const float* __restrict__ qbase, const float* __restrict__ kbase,
          const float* __restrict__ pos, const float* __restrict__ alpha_p)
{
    __shared__ uint32_t As[128][LDA];
    __shared__ uint32_t Bs[128][LDA];

    const int tid = threadIdx.x;
    const int z = blockIdx.z;
    const long long zb = z / H, zh = z % H;

    const float* Ap = qbase + zb * ((long long)S * D) + zh * HD
                    + (long long)blockIdx.y * 128 * D;
    const float* Bp = kbase + zb * ((long long)S * D) + zh * HD
                    + (long long)blockIdx.x * 128 * D;

    float acc[4][4][4];
#pragma unroll
    for (int i = 0; i < 4; i++)
#pragma unroll
        for (int j = 0; j < 4; j++)
#pragma unroll
            for (int e = 0; e < 4; e++) acc[i][j][e] = 0.f;

    mma_mainloop(Ap, D, Bp, D, HD, As, Bs, acc);

    const float scale = 0.08838834764831845f;   // 1/sqrt(128)
    const float alpha = __ldg(alpha_p);
    const float* pb = pos + zb * ((long long)S * 3);

    const int w = tid >> 5, lane = tid & 31;
    const int gid = lane >> 2, tig = lane & 3;
    const int wm = w & 1, wn = w >> 1;
    float* Cz = g_scores + (long long)z * S * S;

    // row positions: 8 rows (4 mt x 2)
    float pi[8][3], sqi[8];
#pragma unroll
    for (int mt = 0; mt < 4; mt++) {
#pragma unroll
        for (int hh = 0; hh < 2; hh++) {
            const long long r = (long long)blockIdx.y * 128 + wm * 64 + mt * 16 + gid + hh * 8;
            const int i = mt * 2 + hh;
            pi[i][0] = __ldg(pb + r * 3 + 0);
            pi[i][1] = __ldg(pb + r * 3 + 1);
            pi[i][2] = __ldg(pb + r * 3 + 2);
            sqi[i] = pi[i][0]*pi[i][0] + pi[i][1]*pi[i][1] + pi[i][2]*pi[i][2];
        }
    }
    // col positions: 8 cols (4 nt x 2)
    float pj[8][3], sqj[8];
#pragma unroll
    for (int nt = 0; nt < 4; nt++) {
#pragma unroll
        for (int e = 0; e < 2; e++) {
            const long long cc = (long long)blockIdx.x * 128 + wn * 32 + nt * 8 + tig * 2 + e;
            const int j = nt * 2 + e;
            pj[j][0] = __ldg(pb + cc * 3 + 0);
            pj[j][1] = __ldg(pb + cc * 3 + 1);
            pj[j][2] = __ldg(pb + cc * 3 + 2);
            sqj[j] = pj[j][0]*pj[j][0] + pj[j][1]*pj[j][1] + pj[j][2]*pj[j][2];
        }
    }

#pragma unroll
    for (int mt = 0; mt < 4; mt++) {
        const long long r0 = (long long)blockIdx.y * 128 + wm * 64 + mt * 16 + gid;
#pragma unroll
        for (int nt = 0; nt < 4; nt++) {
            const long long cb = (long long)blockIdx.x * 128 + wn * 32 + nt * 8 + tig * 2;
            float v[4];
#pragma unroll
            for (int e = 0; e < 4; e++) {
                const int ri = mt * 2 + (e >> 1);
                const int cj = nt * 2 + (e & 1);
                const float dot = pi[ri][0]*pj[cj][0] + pi[ri][1]*pj[cj][1] + pi[ri][2]*pj[cj][2];
                const float d2 = fmaxf(sqi[ri] + sqj[cj] - 2.f * dot, 0.f);
                v[e] = acc[mt][nt][e] * scale - alpha * d2;
            }
            *(float2*)(Cz + r0 * S + cb)       = make_float2(v[0], v[1]);
            *(float2*)(Cz + (r0 + 8) * S + cb) = make_float2(v[2], v[3]);
        }
    }
}

// ------------------------------------------------------------------ transpose [R,C] -> [C,R]
__global__ void transpose_kernel(const float* __restrict__ in, float* __restrict__ out,
                                 int R, int C)
{
    __shared__ float t[32][33];
    const int bx = blockIdx.x * 32, by = blockIdx.y * 32;
    const int tx = threadIdx.x, ty = threadIdx.y;
#pragma unroll
    for (int dy = 0; dy < 32; dy += 8)
        t[ty + dy][tx] = in[(size_t)(by + ty + dy) * C + bx + tx];
    __syncthreads();
#pragma unroll
    for (int dy = 0; dy < 32; dy += 8)
        out[(size_t)(bx + ty + dy) * R + by + tx] = t[tx][ty + dy];
}

// ------------------------------------------------------------------ softmax (row len S)
__global__ void softmax_kernel()
{
    __shared__ float red[256];
    const size_t row = blockIdx.x;
    float* p = g_scores + row * (size_t)S;
    const int t = threadIdx.x;

    float v[8];
    float mx = -INFINITY;
#pragma unroll
    for (int i = 0; i < 8; i++) { v[i] = p[t + i * 256]; mx = fmaxf(mx, v[i]); }
    red[t] = mx; __syncthreads();
    for (int s2 = 128; s2 > 0; s2 >>= 1) {
        if (t < s2) red[t] = fmaxf(red[t], red[t + s2]);
        __syncthreads();
    }
    mx = red[0]; __syncthreads();

    float sum = 0.f;
#pragma unroll
    for (int i = 0; i < 8; i++) { v[i] = expf(v[i] - mx); sum += v[i]; }
    red[t] = sum; __syncthreads();
    for (int s2 = 128; s2 > 0; s2 >>= 1) {
        if (t < s2) red[t] += red[t + s2];
        __syncthreads();
    }
    const float inv = 1.f / red[0];
#pragma unroll
    for (int i = 0; i < 8; i++) p[t + i * 256] = v[i] * inv;
}

// ------------------------------------------------------------------ LayerNorm
__global__ void ln_kernel(const float* __restrict__ x, const float* __restrict__ x2,
                          const float* __restrict__ gamma, const float* __restrict__ beta,
                          float* __restrict__ out)
{
    __shared__ float red[128];
    const int row = blockIdx.x, t = threadIdx.x;
    const size_t base = (size_t)row * D + t * 4;

    float4 v = *(const float4*)(x + base);
    if (x2) {
        float4 w = *(const float4*)(x2 + base);
        v.x += w.x; v.y += w.y; v.z += w.z; v.w += w.w;
    }
    red[t] = v.x + v.y + v.z + v.w; __syncthreads();
    for (int s2 = 64; s2 > 0; s2 >>= 1) {
        if (t < s2) red[t] += red[t + s2];
        __syncthreads();
    }
    const float mean = red[0] * (1.f / D); __syncthreads();

    float dx = v.x - mean, dy = v.y - mean, dz = v.z - mean, dw = v.w - mean;
    red[t] = dx * dx + dy * dy + dz * dz + dw * dw; __syncthreads();
    for (int s2 = 64; s2 > 0; s2 >>= 1) {
        if (t < s2) red[t] += red[t + s2];
        __syncthreads();
    }
    const float inv = rsqrtf(red[0] * (1.f / D) + LN_EPS);

    float4 g = *(const float4*)(gamma + t * 4);
    float4 bt = *(const float4*)(beta + t * 4);
    float4 o;
    o.x = dx * inv * g.x + bt.x;
    o.y = dy * inv * g.y + bt.y;
    o.z = dz * inv * g.z + bt.z;
    o.w = dw * inv * g.w + bt.w;
    *(float4*)(out + base) = o;
}

// ------------------------------------------------------------------ host
extern "C" void kernel_launch(void* const* d_in, const int* in_sizes, int n_in,
                              void* d_out, int out_size)
{
    const float* input   = (const float*)d_in[0];
    const float* pos     = (const float*)d_in[1];
    const float* We      = (const float*)d_in[2];
    const float* be      = (const float*)d_in[3];
    const float* Ws      = (const float*)d_in[4];
    const float* bs      = (const float*)d_in[5];
    const float* gamma   = (const float*)d_in[6];
    const float* beta    = (const float*)d_in[7];
    const float* Wq      = (const float*)d_in[8];
    const float* bq      = (const float*)d_in[9];
    const float* Wk      = (const float*)d_in[10];
    const float* bk      = (const float*)d_in[11];
    const float* Wv      = (const float*)d_in[12];
    const float* bv      = (const float*)d_in[13];
    const float* alpha_p = (const float*)d_in[14];
    float* out = (float*)d_out;

    float *h, *se_pre, *se, *qk, *vt, *ctx, *wet, *wst, *wqkv, *scores;
    cudaGetSymbolAddress((void**)&h,      g_h);
    cudaGetSymbolAddress((void**)&se_pre, g_se_pre);
    cudaGetSymbolAddress((void**)&se,     g_se);
    cudaGetSymbolAddress((void**)&qk,     g_qk);
    cudaGetSymbolAddress((void**)&vt,     g_vt);
    cudaGetSymbolAddress((void**)&ctx,    g_ctx);
    cudaGetSymbolAddress((void**)&wet,    g_wet);
    cudaGetSymbolAddress((void**)&wst,    g_wst);
    cudaGetSymbolAddress((void**)&wqkv,   g_wqkv);
    cudaGetSymbolAddress((void**)&scores, g_scores);

    dim3 tb(32, 8);
    transpose_kernel<<<dim3(D2 / 32, D / 32),  tb>>>(We, wet, D, D2);
    transpose_kernel<<<dim3(D / 32,  D2 / 32), tb>>>(Ws, wst, D2, D);
    transpose_kernel<<<dim3(D / 32,  D / 32),  tb>>>(Wq, wqkv + 0 * D * D, D, D);
    transpose_kernel<<<dim3(D / 32,  D / 32),  tb>>>(Wk, wqkv + 1 * D * D, D, D);
    transpose_kernel<<<dim3(D / 32,  D / 32),  tb>>>(Wv, wqkv + 2 * D * D, D, D);

    // 1. h = relu(input @ We + be)
    mma_gemm<<<dim3(D2 / 128, M_TOT / 128, 1), 256>>>(
        input, D, 0, 0,  wet, D, 0, 0,  h, D2, 0, 0,
        be, be, be, nullptr, nullptr, -1, 1, D, 1);
    // 2. se_pre = input + h @ Ws + bs
    mma_gemm<<<dim3(D / 128, M_TOT / 128, 1), 256>>>(
        h, D2, 0, 0,  wst, D2, 0, 0,  se_pre, D, 0, 0,
        bs, bs, bs, input, nullptr, -1, 0, D2, 1);
    // 3. se = LN(se_pre)
    ln_kernel<<<M_TOT, 128>>>(se_pre, nullptr, gamma, beta, se);
    // 4. q/k/v (z=0,1,2); v written transposed into g_vt
    mma_gemm<<<dim3(D / 128, M_TOT / 128, 3), 256>>>(
        se, D, 0, 0,
        wqkv, D, (long long)D * D, 0,
        qk, D, (long long)M_TOT * D, 0,
        bq, bk, bv, nullptr, vt, 2, 0, D, 1);
    // 5. scores
    mma_score<<<dim3(S / 128, S / 128, Bb * H), 256>>>(qk, qk + (size_t)M_TOT * D, pos, alpha_p);
    // 6. softmax
    softmax_kernel<<<Bb * H * S, 256>>>();
    // 7. ctx = P @ V   (Bt = g_vt, [HD,S] rows per head)
    mma_gemm<<<dim3(1, S / 128, Bb * H), 256>>>(
        scores, S, (long long)H * S * S, (long long)S * S,
        vt, S, (long long)H * HD * S, (long long)HD * S,
        ctx, D, (long long)S * D, HD,
        nullptr, nullptr, nullptr, nullptr, nullptr, -1, 0, S, H);
    // 8. out = LN(se + ctx)
    ln_kernel<<<M_TOT, 128>>>(se, ctx, gamma, beta, out);
}

// round 4
// speedup vs baseline: 3.1068x; 1.1183x over previous
#include <cuda_runtime.h>
#include <math.h>
#include <stdint.h>

#define Bb 4
#define S 2048
#define D 512
#define H 4
#define HD 128
#define M_TOT (Bb*S)      // 8192
#define D2 (2*D)          // 1024
#define LN_EPS 1e-5f

// ------------------------------------------------------------------ scratch
__device__ float g_h[(size_t)M_TOT * D2];
__device__ float g_se_pre[(size_t)M_TOT * D];
__device__ float g_se[(size_t)M_TOT * D];
__device__ float g_qk[2 * (size_t)M_TOT * D];     // q then k
__device__ float g_vt[(size_t)M_TOT * D];         // [B][D][S] (V^T per batch)
__device__ float g_ctx[(size_t)M_TOT * D];
__device__ float g_wet[1024 * 512];               // We^T [1024,512]
__device__ float g_wst[512 * 1024];               // Ws^T [512,1024]
__device__ float g_wqkv[3 * 512 * 512];           // Wq^T,Wk^T,Wv^T

// ------------------------------------------------------------------ utils
__device__ __forceinline__ uint32_t f2tf(float f) {
    uint32_t u; asm("cvt.rna.tf32.f32 %0, %1;" : "=r"(u) : "f"(f)); return u;
}

__device__ __forceinline__ void mma_tf32(float c[4], const uint32_t a[4], const uint32_t b[2]) {
    asm volatile(
        "mma.sync.aligned.m16n8k8.row.col.f32.tf32.tf32.f32 "
        "{%0,%1,%2,%3}, {%4,%5,%6,%7}, {%8,%9}, {%0,%1,%2,%3};"
        : "+f"(c[0]), "+f"(c[1]), "+f"(c[2]), "+f"(c[3])
        : "r"(a[0]), "r"(a[1]), "r"(a[2]), "r"(a[3]), "r"(b[0]), "r"(b[1]));
}

#define LDA 36    // padded smem leading dim for 32-wide chunks (GEMM kernels)
#define FLDA 132  // padded smem leading dim for 128-wide tiles (flash kernel)

// ================================================================== GEMM path
// (unchanged from R3 — proven correct/fast for FFN + QKV)
__device__ __forceinline__ void mma_mainloop(
    const float* __restrict__ Ap, long long lda,
    const float* __restrict__ Bp, long long ldb,
    int K, uint32_t (*As)[LDA], uint32_t (*Bs)[LDA], float acc[4][4][4])
{
    const int tid  = threadIdx.x;
    const int w    = tid >> 5, lane = tid & 31;
    const int gid  = lane >> 2, tig = lane & 3;
    const int wm   = w & 1, wn = w >> 1;

    const int srow = tid >> 3;
    const int sc4  = (tid & 7) * 4;

    float4 pa[4], pb[4];
#pragma unroll
    for (int i = 0; i < 4; i++) {
        pa[i] = *(const float4*)(Ap + (long long)(srow + i * 32) * lda + sc4);
        pb[i] = *(const float4*)(Bp + (long long)(srow + i * 32) * ldb + sc4);
    }

    const int nchunk = K >> 5;
    for (int c = 0; c < nchunk; c++) {
        __syncthreads();
#pragma unroll
        for (int i = 0; i < 4; i++) {
            const int r = srow + i * 32;
            As[r][sc4 + 0] = f2tf(pa[i].x); As[r][sc4 + 1] = f2tf(pa[i].y);
            As[r][sc4 + 2] = f2tf(pa[i].z); As[r][sc4 + 3] = f2tf(pa[i].w);
            Bs[r][sc4 + 0] = f2tf(pb[i].x); Bs[r][sc4 + 1] = f2tf(pb[i].y);
            Bs[r][sc4 + 2] = f2tf(pb[i].z); Bs[r][sc4 + 3] = f2tf(pb[i].w);
        }
        __syncthreads();

        if (c + 1 < nchunk) {
            const int k0 = (c + 1) << 5;
#pragma unroll
            for (int i = 0; i < 4; i++) {
                pa[i] = *(const float4*)(Ap + (long long)(srow + i * 32) * lda + k0 + sc4);
                pb[i] = *(const float4*)(Bp + (long long)(srow + i * 32) * ldb + k0 + sc4);
            }
        }

#pragma unroll
        for (int k8 = 0; k8 < 4; k8++) {
            const int kb = k8 * 8;
            uint32_t af[4][4], bf[4][2];
#pragma unroll
            for (int mt = 0; mt < 4; mt++) {
                const int r = wm * 64 + mt * 16 + gid;
                af[mt][0] = As[r][kb + tig];
                af[mt][1] = As[r + 8][kb + tig];
                af[mt][2] = As[r][kb + tig + 4];
                af[mt][3] = As[r + 8][kb + tig + 4];
            }
#pragma unroll
            for (int nt = 0; nt < 4; nt++) {
                const int n = wn * 32 + nt * 8 + gid;
                bf[nt][0] = Bs[n][kb + tig];
                bf[nt][1] = Bs[n][kb + tig + 4];
            }
#pragma unroll
            for (int mt = 0; mt < 4; mt++)
#pragma unroll
                for (int nt = 0; nt < 4; nt++)
                    mma_tf32(acc[mt][nt], af[mt], bf[nt]);
        }
    }
}

__global__ void __launch_bounds__(256)
mma_gemm(const float* __restrict__ A, long long lda, long long Azb, long long Azh,
         const float* __restrict__ Bt, long long ldb, long long Bzb, long long Bzh,
         float* __restrict__ C, long long ldc, long long Czb, long long Czh,
         const float* b0, const float* b1, const float* b2,
         const float* __restrict__ resid, float* __restrict__ vt, int vt_z,
         int relu, int K, int zdiv)
{
    __shared__ uint32_t As[128][LDA];
    __shared__ uint32_t Bs[128][LDA];

    const int tid = threadIdx.x;
    const int z = blockIdx.z;
    const long long zb = z / zdiv, zh = z % zdiv;

    const float* Ap = A + zb * Azb + zh * Azh + (long long)blockIdx.y * 128 * lda;
    const float* Bp = Bt + zb * Bzb + zh * Bzh + (long long)blockIdx.x * 128 * ldb;

    float acc[4][4][4];
#pragma unroll
    for (int i = 0; i < 4; i++)
#pragma unroll
        for (int j = 0; j < 4; j++)
#pragma unroll
            for (int e = 0; e < 4; e++) acc[i][j][e] = 0.f;

    mma_mainloop(Ap, lda, Bp, ldb, K, As, Bs, acc);

    const float* bias = (z == 0) ? b0 : (z == 1) ? b1 : b2;
    const int w = tid >> 5, lane = tid & 31;
    const int gid = lane >> 2, tig = lane & 3;
    const int wm = w & 1, wn = w >> 1;
    float* Cz = C + zb * Czb + zh * Czh;
    const bool dotrans = (vt != nullptr) && (z == vt_z);

#pragma unroll
    for (int mt = 0; mt < 4; mt++) {
        const long long r0 = (long long)blockIdx.y * 128 + wm * 64 + mt * 16 + gid;
        const long long r1 = r0 + 8;
#pragma unroll
        for (int nt = 0; nt < 4; nt++) {
            const long long cb = (long long)blockIdx.x * 128 + wn * 32 + nt * 8 + tig * 2;
            float v0 = acc[mt][nt][0], v1 = acc[mt][nt][1];
            float v2 = acc[mt][nt][2], v3 = acc[mt][nt][3];
            if (bias) {
                const float bx = __ldg(bias + cb), by = __ldg(bias + cb + 1);
                v0 += bx; v1 += by; v2 += bx; v3 += by;
            }
            if (resid) {
                const float2 q0 = *(const float2*)(resid + r0 * ldc + cb);
                const float2 q1 = *(const float2*)(resid + r1 * ldc + cb);
                v0 += q0.x; v1 += q0.y; v2 += q1.x; v3 += q1.y;
            }
            if (relu) {
                v0 = fmaxf(v0, 0.f); v1 = fmaxf(v1, 0.f);
                v2 = fmaxf(v2, 0.f); v3 = fmaxf(v3, 0.f);
            }
            if (dotrans) {
                const long long b0r = r0 >> 11, s0 = r0 & (S - 1);
                const long long b1r = r1 >> 11, s1 = r1 & (S - 1);
                float* vb0 = vt + b0r * ((long long)D * S);
                float* vb1 = vt + b1r * ((long long)D * S);
                vb0[cb * S + s0] = v0; vb0[(cb + 1) * S + s0] = v1;
                vb1[cb * S + s1] = v2; vb1[(cb + 1) * S + s1] = v3;
            } else {
                *(float2*)(Cz + r0 * ldc + cb) = make_float2(v0, v1);
                *(float2*)(Cz + r1 * ldc + cb) = make_float2(v2, v3);
            }
        }
    }
}

// ================================================================== flash attention
// One CTA = 128 Q rows for one (b,h). Loops over 16 KV tiles of 128.
// Warp tile = 16 rows x 128 cols: softmax rows are warp-local (quad shuffles only).
// P@V A-fragments built in-register from S accumulators via quad shuffles.
__global__ void __launch_bounds__(256)
flash_kernel(const float* __restrict__ qbase, const float* __restrict__ kbase,
             const float* __restrict__ pos, const float* __restrict__ alpha_p)
{
    extern __shared__ uint32_t sm[];
    uint32_t (*Qs)[FLDA] = (uint32_t(*)[FLDA])sm;
    uint32_t (*Ks)[FLDA] = (uint32_t(*)[FLDA])(sm + 128 * FLDA);
    uint32_t (*Vs)[FLDA] = (uint32_t(*)[FLDA])(sm + 2 * 128 * FLDA);
    float4* spos = (float4*)(sm + 3 * 128 * FLDA);

    const int tid  = threadIdx.x;
    const int w    = tid >> 5, lane = tid & 31;
    const int gid  = lane >> 2, tig = lane & 3;
    const int z    = blockIdx.y;
    const long long b = z / H, h = z % H;
    const int qt   = blockIdx.x;

    const float* Qp = qbase + b * ((long long)S * D) + h * HD + (long long)qt * 128 * D;
    const float* Kb = kbase + b * ((long long)S * D) + h * HD;
    const float* Vb = g_vt + b * ((long long)D * S) + (long long)h * HD * S;  // [hd][s]
    const float* pb = pos + b * ((long long)S * 3);

    // stage Q tile (tf32), coalesced: warp w covers rows w, w+8, ..., lane -> 4 cols
#pragma unroll
    for (int i = 0; i < 16; i++) {
        const int r = w + 8 * i;
        const float4 v = *(const float4*)(Qp + (long long)r * D + lane * 4);
        uint32_t* dst = &Qs[r][lane * 4];
        dst[0] = f2tf(v.x); dst[1] = f2tf(v.y); dst[2] = f2tf(v.z); dst[3] = f2tf(v.w);
    }

    // fixed row positions (2 rows per thread)
    const long long gr0 = (long long)qt * 128 + w * 16 + gid;
    const long long gr1 = gr0 + 8;
    const float px0 = __ldg(pb + gr0 * 3), py0 = __ldg(pb + gr0 * 3 + 1), pz0 = __ldg(pb + gr0 * 3 + 2);
    const float px1 = __ldg(pb + gr1 * 3), py1 = __ldg(pb + gr1 * 3 + 1), pz1 = __ldg(pb + gr1 * 3 + 2);
    const float sq0 = px0 * px0 + py0 * py0 + pz0 * pz0;
    const float sq1 = px1 * px1 + py1 * py1 + pz1 * pz1;

    float oacc[16][4];
#pragma unroll
    for (int i = 0; i < 16; i++)
#pragma unroll
        for (int e = 0; e < 4; e++) oacc[i][e] = 0.f;
    float m0 = -1e30f, m1 = -1e30f, l0 = 0.f, l1 = 0.f;

    const float scale = 0.08838834764831845f;  // 1/sqrt(128)
    const float alpha = __ldg(alpha_p);
    const int src0 = (lane & ~3) | (tig >> 1);
    const int src1 = src0 + 2;
    const bool odd = (tig & 1);

    for (int j = 0; j < 16; j++) {
        __syncthreads();
        // stage K tile [s_kv][hd] and V^T tile [hd][s_kv]
        const float* Kp = Kb + (long long)j * 128 * D;
#pragma unroll
        for (int i = 0; i < 16; i++) {
            const int r = w + 8 * i;
            const float4 v = *(const float4*)(Kp + (long long)r * D + lane * 4);
            uint32_t* dk = &Ks[r][lane * 4];
            dk[0] = f2tf(v.x); dk[1] = f2tf(v.y); dk[2] = f2tf(v.z); dk[3] = f2tf(v.w);
            const float4 u = *(const float4*)(Vb + (long long)r * S + j * 128 + lane * 4);
            uint32_t* dv = &Vs[r][lane * 4];
            dv[0] = f2tf(u.x); dv[1] = f2tf(u.y); dv[2] = f2tf(u.z); dv[3] = f2tf(u.w);
        }
        if (tid < 128) {
            const long long c = (long long)j * 128 + tid;
            const float x = pb[c * 3], y = pb[c * 3 + 1], zz = pb[c * 3 + 2];
            spos[tid] = make_float4(x, y, zz, x * x + y * y + zz * zz);
        }
        __syncthreads();

        // ---- S = Q @ K^T ----
        float sacc[16][4];
#pragma unroll
        for (int i = 0; i < 16; i++)
#pragma unroll
            for (int e = 0; e < 4; e++) sacc[i][e] = 0.f;

#pragma unroll
        for (int g = 0; g < 16; g++) {
            const int kb = g * 8;
            const int ra = w * 16 + gid;
            uint32_t af[4];
            af[0] = Qs[ra][kb + tig];
            af[1] = Qs[ra + 8][kb + tig];
            af[2] = Qs[ra][kb + tig + 4];
            af[3] = Qs[ra + 8][kb + tig + 4];
#pragma unroll
            for (int nt = 0; nt < 16; nt++) {
                uint32_t bf[2] = { Ks[nt * 8 + gid][kb + tig], Ks[nt * 8 + gid][kb + tig + 4] };
                mma_tf32(sacc[nt], af, bf);
            }
        }

        // ---- bias + online softmax ----
        float nm0 = m0, nm1 = m1;
#pragma unroll
        for (int nt = 0; nt < 16; nt++) {
            const int c0 = nt * 8 + tig * 2;
            const float4 q0 = spos[c0];
            const float4 q1 = spos[c0 + 1];
            float d;
            d = fmaxf(sq0 + q0.w - 2.f * (px0 * q0.x + py0 * q0.y + pz0 * q0.z), 0.f);
            sacc[nt][0] = sacc[nt][0] * scale - alpha * d;
            d = fmaxf(sq0 + q1.w - 2.f * (px0 * q1.x + py0 * q1.y + pz0 * q1.z), 0.f);
            sacc[nt][1] = sacc[nt][1] * scale - alpha * d;
            d = fmaxf(sq1 + q0.w - 2.f * (px1 * q0.x + py1 * q0.y + pz1 * q0.z), 0.f);
            sacc[nt][2] = sacc[nt][2] * scale - alpha * d;
            d = fmaxf(sq1 + q1.w - 2.f * (px1 * q1.x + py1 * q1.y + pz1 * q1.z), 0.f);
            sacc[nt][3] = sacc[nt][3] * scale - alpha * d;
            nm0 = fmaxf(nm0, fmaxf(sacc[nt][0], sacc[nt][1]));
            nm1 = fmaxf(nm1, fmaxf(sacc[nt][2], sacc[nt][3]));
        }
        nm0 = fmaxf(nm0, __shfl_xor_sync(0xffffffffu, nm0, 1));
        nm0 = fmaxf(nm0, __shfl_xor_sync(0xffffffffu, nm0, 2));
        nm1 = fmaxf(nm1, __shfl_xor_sync(0xffffffffu, nm1, 1));
        nm1 = fmaxf(nm1, __shfl_xor_sync(0xffffffffu, nm1, 2));

        const float f0 = __expf(m0 - nm0);
        const float f1 = __expf(m1 - nm1);
        m0 = nm0; m1 = nm1;

        float rs0 = 0.f, rs1 = 0.f;
#pragma unroll
        for (int nt = 0; nt < 16; nt++) {
            sacc[nt][0] = __expf(sacc[nt][0] - nm0);
            sacc[nt][1] = __expf(sacc[nt][1] - nm0);
            sacc[nt][2] = __expf(sacc[nt][2] - nm1);
            sacc[nt][3] = __expf(sacc[nt][3] - nm1);
            rs0 += sacc[nt][0] + sacc[nt][1];
            rs1 += sacc[nt][2] + sacc[nt][3];
        }
        rs0 += __shfl_xor_sync(0xffffffffu, rs0, 1);
        rs0 += __shfl_xor_sync(0xffffffffu, rs0, 2);
        rs1 += __shfl_xor_sync(0xffffffffu, rs1, 1);
        rs1 += __shfl_xor_sync(0xffffffffu, rs1, 2);
        l0 = l0 * f0 + rs0;
        l1 = l1 * f1 + rs1;

#pragma unroll
        for (int i = 0; i < 16; i++) {
            oacc[i][0] *= f0; oacc[i][1] *= f0;
            oacc[i][2] *= f1; oacc[i][3] *= f1;
        }

        // ---- O += P @ V ----
#pragma unroll
        for (int g = 0; g < 16; g++) {
            const float u00 = __shfl_sync(0xffffffffu, sacc[g][0], src0);
            const float u01 = __shfl_sync(0xffffffffu, sacc[g][1], src0);
            const float u10 = __shfl_sync(0xffffffffu, sacc[g][0], src1);
            const float u11 = __shfl_sync(0xffffffffu, sacc[g][1], src1);
            const float u20 = __shfl_sync(0xffffffffu, sacc[g][2], src0);
            const float u21 = __shfl_sync(0xffffffffu, sacc[g][3], src0);
            const float u30 = __shfl_sync(0xffffffffu, sacc[g][2], src1);
            const float u31 = __shfl_sync(0xffffffffu, sacc[g][3], src1);
            uint32_t af[4];
            af[0] = f2tf(odd ? u01 : u00);   // P[row0][tig]
            af[1] = f2tf(odd ? u21 : u20);   // P[row1][tig]
            af[2] = f2tf(odd ? u11 : u10);   // P[row0][tig+4]
            af[3] = f2tf(odd ? u31 : u30);   // P[row1][tig+4]
            const int kb = g * 8;
#pragma unroll
            for (int ng = 0; ng < 16; ng++) {
                uint32_t bf[2] = { Vs[ng * 8 + gid][kb + tig], Vs[ng * 8 + gid][kb + tig + 4] };
                mma_tf32(oacc[ng], af, bf);
            }
        }
    }

    // ---- epilogue: O / l -> ctx ----
    const float i0 = 1.f / l0, i1 = 1.f / l1;
    float* Cb = g_ctx + b * ((long long)S * D) + h * HD;
    const long long cr0 = (long long)qt * 128 + w * 16 + gid;
#pragma unroll
    for (int ng = 0; ng < 16; ng++) {
        const int col = ng * 8 + tig * 2;
        *(float2*)(Cb + cr0 * D + col)       = make_float2(oacc[ng][0] * i0, oacc[ng][1] * i0);
        *(float2*)(Cb + (cr0 + 8) * D + col) = make_float2(oacc[ng][2] * i1, oacc[ng][3] * i1);
    }
}

// ------------------------------------------------------------------ transpose [R,C] -> [C,R]
__global__ void transpose_kernel(const float* __restrict__ in, float* __restrict__ out,
                                 int R, int C)
{
    __shared__ float t[32][33];
    const int bx = blockIdx.x * 32, by = blockIdx.y * 32;
    const int tx = threadIdx.x, ty = threadIdx.y;
#pragma unroll
    for (int dy = 0; dy < 32; dy += 8)
        t[ty + dy][tx] = in[(size_t)(by + ty + dy) * C + bx + tx];
    __syncthreads();
#pragma unroll
    for (int dy = 0; dy < 32; dy += 8)
        out[(size_t)(bx + ty + dy) * R + by + tx] = t[tx][ty + dy];
}

// ------------------------------------------------------------------ LayerNorm
__global__ void ln_kernel(const float* __restrict__ x, const float* __restrict__ x2,
                          const float* __restrict__ gamma, const float* __restrict__ beta,
                          float* __restrict__ out)
{
    __shared__ float red[128];
    const int row = blockIdx.x, t = threadIdx.x;
    const size_t base = (size_t)row * D + t * 4;

    float4 v = *(const float4*)(x + base);
    if (x2) {
        float4 w = *(const float4*)(x2 + base);
        v.x += w.x; v.y += w.y; v.z += w.z; v.w += w.w;
    }
    red[t] = v.x + v.y + v.z + v.w; __syncthreads();
    for (int s2 = 64; s2 > 0; s2 >>= 1) {
        if (t < s2) red[t] += red[t + s2];
        __syncthreads();
    }
    const float mean = red[0] * (1.f / D); __syncthreads();

    float dx = v.x - mean, dy = v.y - mean, dz = v.z - mean, dw = v.w - mean;
    red[t] = dx * dx + dy * dy + dz * dz + dw * dw; __syncthreads();
    for (int s2 = 64; s2 > 0; s2 >>= 1) {
        if (t < s2) red[t] += red[t + s2];
        __syncthreads();
    }
    const float inv = rsqrtf(red[0] * (1.f / D) + LN_EPS);

    float4 g = *(const float4*)(gamma + t * 4);
    float4 bt = *(const float4*)(beta + t * 4);
    float4 o;
    o.x = dx * inv * g.x + bt.x;
    o.y = dy * inv * g.y + bt.y;
    o.z = dz * inv * g.z + bt.z;
    o.w = dw * inv * g.w + bt.w;
    *(float4*)(out + base) = o;
}

// ------------------------------------------------------------------ host
extern "C" void kernel_launch(void* const* d_in, const int* in_sizes, int n_in,
                              void* d_out, int out_size)
{
    const float* input   = (const float*)d_in[0];
    const float* pos     = (const float*)d_in[1];
    const float* We      = (const float*)d_in[2];
    const float* be      = (const float*)d_in[3];
    const float* Ws      = (const float*)d_in[4];
    const float* bs      = (const float*)d_in[5];
    const float* gamma   = (const float*)d_in[6];
    const float* beta    = (const float*)d_in[7];
    const float* Wq      = (const float*)d_in[8];
    const float* bq      = (const float*)d_in[9];
    const float* Wk      = (const float*)d_in[10];
    const float* bk      = (const float*)d_in[11];
    const float* Wv      = (const float*)d_in[12];
    const float* bv      = (const float*)d_in[13];
    const float* alpha_p = (const float*)d_in[14];
    float* out = (float*)d_out;

    float *h, *se_pre, *se, *qk, *vt, *ctx, *wet, *wst, *wqkv;
    cudaGetSymbolAddress((void**)&h,      g_h);
    cudaGetSymbolAddress((void**)&se_pre, g_se_pre);
    cudaGetSymbolAddress((void**)&se,     g_se);
    cudaGetSymbolAddress((void**)&qk,     g_qk);
    cudaGetSymbolAddress((void**)&vt,     g_vt);
    cudaGetSymbolAddress((void**)&ctx,    g_ctx);
    cudaGetSymbolAddress((void**)&wet,    g_wet);
    cudaGetSymbolAddress((void**)&wst,    g_wst);
    cudaGetSymbolAddress((void**)&wqkv,   g_wqkv);

    static bool attr_set = false;
    const int flash_smem = (3 * 128 * FLDA) * 4 + 128 * 16;   // 204800 B
    if (!attr_set) {
        cudaFuncSetAttribute(flash_kernel, cudaFuncAttributeMaxDynamicSharedMemorySize, flash_smem);
        attr_set = true;
    }

    dim3 tb(32, 8);
    transpose_kernel<<<dim3(D2 / 32, D / 32),  tb>>>(We, wet, D, D2);
    transpose_kernel<<<dim3(D / 32,  D2 / 32), tb>>>(Ws, wst, D2, D);
    transpose_kernel<<<dim3(D / 32,  D / 32),  tb>>>(Wq, wqkv + 0 * D * D, D, D);
    transpose_kernel<<<dim3(D / 32,  D / 32),  tb>>>(Wk, wqkv + 1 * D * D, D, D);
    transpose_kernel<<<dim3(D / 32,  D / 32),  tb>>>(Wv, wqkv + 2 * D * D, D, D);

    // 1. h = relu(input @ We + be)
    mma_gemm<<<dim3(D2 / 128, M_TOT / 128, 1), 256>>>(
        input, D, 0, 0,  wet, D, 0, 0,  h, D2, 0, 0,
        be, be, be, nullptr, nullptr, -1, 1, D, 1);
    // 2. se_pre = input + h @ Ws + bs
    mma_gemm<<<dim3(D / 128, M_TOT / 128, 1), 256>>>(
        h, D2, 0, 0,  wst, D2, 0, 0,  se_pre, D, 0, 0,
        bs, bs, bs, input, nullptr, -1, 0, D2, 1);
    // 3. se = LN(se_pre)
    ln_kernel<<<M_TOT, 128>>>(se_pre, nullptr, gamma, beta, se);
    // 4. q/k/v (z=0,1,2); v written transposed into g_vt
    mma_gemm<<<dim3(D / 128, M_TOT / 128, 3), 256>>>(
        se, D, 0, 0,
        wqkv, D, (long long)D * D, 0,
        qk, D, (long long)M_TOT * D, 0,
        bq, bk, bv, nullptr, vt, 2, 0, D, 1);
    // 5-7. fused flash attention -> ctx
    flash_kernel<<<dim3(S / 128, Bb * H), 256, flash_smem>>>(
        qk, qk + (size_t)M_TOT * D, pos, alpha_p);
    // 8. out = LN(se + ctx)
    ln_kernel<<<M_TOT, 128>>>(se, ctx, gamma, beta, out);
}